// round 6
// baseline (speedup 1.0000x reference)
#include <cuda_runtime.h>
#include <cstddef>

// Sparsemax over last dim: rows of D=512 fp32, one warp per row.
// R6: warm-started Michelot + warp-level candidate compaction.
//   tau* >= max(x) - 1, so support(x) subset of C = {x_i > max - 1}, |C| ~ 5.
//   Compact C into smem once (ballot/popc), then iterate Michelot as a
//   uniform scalar loop over C (broadcast LDS, no shuffles, no redux).
//   Count-stable termination => exact tau*.

static constexpr int D    = 512;   // elements per row
static constexpr int VPT  = 4;     // float4 loads per thread (4*4*32 = 512)
static constexpr int MAXC = 32;    // candidate capacity; fallback if exceeded
static constexpr int WPB  = 8;     // warps (rows) per block

__global__ __launch_bounds__(WPB * 32) void sparsemax_kernel(
    const float* __restrict__ x, float* __restrict__ y, int nrows)
{
    __shared__ float cand[WPB][MAXC];

    const int gwarp = (blockIdx.x * blockDim.x + threadIdx.x) >> 5;
    if (gwarp >= nrows) return;
    const int lane = threadIdx.x & 31;
    float* __restrict__ cw = cand[threadIdx.x >> 5];

    const float4* __restrict__ xr =
        reinterpret_cast<const float4*>(x) + (size_t)gwarp * (D / 4);
    float4* __restrict__ yr =
        reinterpret_cast<float4*>(y) + (size_t)gwarp * (D / 4);

    // Pass 1: coalesced streaming loads; row max.
    float4 v[VPT];
    float m = -3.402823466e38f;
#pragma unroll
    for (int j = 0; j < VPT; j++) {
        float4 t = __ldcs(&xr[lane + 32 * j]);
        v[j] = t;
        m = fmaxf(m, fmaxf(fmaxf(t.x, t.y), fmaxf(t.z, t.w)));
    }
#pragma unroll
    for (int o = 16; o > 0; o >>= 1)
        m = fmaxf(m, __shfl_xor_sync(0xffffffffu, m, o));

    const float tau0 = m - 1.0f;          // valid lower bound on tau*
    const unsigned lt = (1u << lane) - 1u;

    // Pass 2: compact candidates {x > tau0} into smem (warp-synchronous).
    // base is warp-uniform (same ballots on every lane) => c0 for free.
    int base = 0;
#pragma unroll
    for (int j = 0; j < VPT; j++) {
        const float vals[4] = {v[j].x, v[j].y, v[j].z, v[j].w};
#pragma unroll
        for (int k = 0; k < 4; k++) {
            const bool p = vals[k] > tau0;
            const unsigned bal = __ballot_sync(0xffffffffu, p);
            if (p) {
                const int pos = base + __popc(bal & lt);
                if (pos < MAXC) cw[pos] = vals[k];
            }
            base += __popc(bal);
        }
    }
    __syncwarp();

    float tau = tau0;
    if (base <= MAXC) {
        // Uniform scalar Michelot over the tiny candidate set.
        // All lanes read identical smem (broadcast) => identical tau, no
        // cross-lane reductions needed. First iteration: all cands > tau0.
        int prev = -1;
        for (;;) {
            float s = 0.0f;
            int c = 0;
            for (int i = 0; i < base; i++) {
                const float t = cw[i];
                if (t > tau) { s += t; c++; }
            }
            if (c == prev) break;   // same count => same set => fixed point
            prev = c;
            tau = (s - 1.0f) / (float)c;
        }
    } else {
        // Fallback (warp-uniform branch, astronomically rare): register-scan
        // Michelot with cross-lane reductions — the proven R5 path.
        int prev = -1;
        for (;;) {
            float s = 0.0f;
            int c = 0;
#pragma unroll
            for (int j = 0; j < VPT; j++) {
                if (v[j].x > tau) { s += v[j].x; c++; }
                if (v[j].y > tau) { s += v[j].y; c++; }
                if (v[j].z > tau) { s += v[j].z; c++; }
                if (v[j].w > tau) { s += v[j].w; c++; }
            }
#pragma unroll
            for (int o = 16; o > 0; o >>= 1)
                s += __shfl_xor_sync(0xffffffffu, s, o);
            c = __reduce_add_sync(0xffffffffu, c);
            if (c == prev) break;
            prev = c;
            tau = (s - 1.0f) / (float)c;
        }
    }

    // Pass 3: streaming vector stores of max(0, x - tau).
#pragma unroll
    for (int j = 0; j < VPT; j++) {
        const float4 t = v[j];
        float4 o;
        o.x = fmaxf(0.0f, t.x - tau);
        o.y = fmaxf(0.0f, t.y - tau);
        o.z = fmaxf(0.0f, t.z - tau);
        o.w = fmaxf(0.0f, t.w - tau);
        __stcs(&yr[lane + 32 * j], o);
    }
}

extern "C" void kernel_launch(void* const* d_in, const int* in_sizes, int n_in,
                              void* d_out, int out_size)
{
    const float* x = (const float*)d_in[0];
    float* y = (float*)d_out;
    const int nrows = in_sizes[0] / D;              // 32*4096 = 131072
    const int blocks = (nrows + WPB - 1) / WPB;
    sparsemax_kernel<<<blocks, WPB * 32>>>(x, y, nrows);
}

// round 7
// speedup vs baseline: 1.3148x; 1.3148x over previous
#include <cuda_runtime.h>
#include <cstddef>

// Sparsemax over last dim: rows of D=512 fp32, one warp per row.
// R7: warm-started Michelot with per-lane online top-3 tracking.
//   tau* >= max(x) - 1, so support(x) subset of C = {x_i > max - 1}, |C| ~ 5.
//   Per-lane candidate count ~ Poisson(0.17): >=3 per lane is ~8.5e-4, so
//   with P ~ 97% per row every lane's candidates fit in its top-2 registers
//   (verified exactly via ballot(a3 > tau0)). Michelot iterations then touch
//   only 2 registers/lane. Rare overflow -> proven full register-scan path.
//   Count-stable termination => exact tau*.

static constexpr int D   = 512;   // elements per row
static constexpr int VPT = 4;     // float4 loads per thread (4*4*32 = 512)
static constexpr int WPB = 8;     // warps (rows) per block

__global__ __launch_bounds__(WPB * 32) void sparsemax_kernel(
    const float* __restrict__ x, float* __restrict__ y, int nrows)
{
    const int gwarp = (blockIdx.x * blockDim.x + threadIdx.x) >> 5;
    if (gwarp >= nrows) return;
    const int lane = threadIdx.x & 31;

    const float4* __restrict__ xr =
        reinterpret_cast<const float4*>(x) + (size_t)gwarp * (D / 4);
    float4* __restrict__ yr =
        reinterpret_cast<float4*>(y) + (size_t)gwarp * (D / 4);

    // Pass 1: coalesced streaming loads + branchless per-lane top-3.
    // (a1 >= a2 >= a3 after each insert; a1 doubles as the lane max.)
    float4 v[VPT];
    float a1 = -3.402823466e38f, a2 = a1, a3 = a1;
#pragma unroll
    for (int j = 0; j < VPT; j++) {
        const float4 t = __ldcs(&xr[lane + 32 * j]);
        v[j] = t;
        const float e[4] = {t.x, t.y, t.z, t.w};
#pragma unroll
        for (int k = 0; k < 4; k++) {
            const float n1 = fmaxf(a1, e[k]);
            const float r1 = fminf(a1, e[k]);
            const float n2 = fmaxf(a2, r1);
            const float r2 = fminf(a2, r1);
            a3 = fmaxf(a3, r2);
            a1 = n1; a2 = n2;
        }
    }
    float m = a1;
#pragma unroll
    for (int o = 16; o > 0; o >>= 1)
        m = fmaxf(m, __shfl_xor_sync(0xffffffffu, m, o));

    const float tau0 = m - 1.0f;    // valid lower bound on tau*
    float tau = tau0;

    if (__ballot_sync(0xffffffffu, a3 > tau0) == 0u) {
        // Fast path: every lane's candidates are within {a1, a2}.
        // Iterations only ever raise tau, so the containment stays valid.
        int prev = -1;
        for (;;) {
            float s = 0.0f;
            int c = 0;
            if (a1 > tau) { s += a1; c++; }
            if (a2 > tau) { s += a2; c++; }
#pragma unroll
            for (int o = 16; o > 0; o >>= 1)
                s += __shfl_xor_sync(0xffffffffu, s, o);
            c = __reduce_add_sync(0xffffffffu, c);   // REDUX.SUM
            if (c == prev) break;   // same count => same set => fixed point
            prev = c;
            tau = (s - 1.0f) / (float)c;
        }
    } else {
        // Rare overflow path (warp-uniform branch): full register-scan
        // Michelot — the proven R5 loop.
        int prev = -1;
        for (;;) {
            float s = 0.0f;
            int c = 0;
#pragma unroll
            for (int j = 0; j < VPT; j++) {
                if (v[j].x > tau) { s += v[j].x; c++; }
                if (v[j].y > tau) { s += v[j].y; c++; }
                if (v[j].z > tau) { s += v[j].z; c++; }
                if (v[j].w > tau) { s += v[j].w; c++; }
            }
#pragma unroll
            for (int o = 16; o > 0; o >>= 1)
                s += __shfl_xor_sync(0xffffffffu, s, o);
            c = __reduce_add_sync(0xffffffffu, c);
            if (c == prev) break;
            prev = c;
            tau = (s - 1.0f) / (float)c;
        }
    }

    // Pass 2: streaming vector stores of max(0, x - tau).
#pragma unroll
    for (int j = 0; j < VPT; j++) {
        const float4 t = v[j];
        float4 o;
        o.x = fmaxf(0.0f, t.x - tau);
        o.y = fmaxf(0.0f, t.y - tau);
        o.z = fmaxf(0.0f, t.z - tau);
        o.w = fmaxf(0.0f, t.w - tau);
        __stcs(&yr[lane + 32 * j], o);
    }
}

extern "C" void kernel_launch(void* const* d_in, const int* in_sizes, int n_in,
                              void* d_out, int out_size)
{
    const float* x = (const float*)d_in[0];
    float* y = (float*)d_out;
    const int nrows = in_sizes[0] / D;              // 32*4096 = 131072
    const int blocks = (nrows + WPB - 1) / WPB;
    sparsemax_kernel<<<blocks, WPB * 32>>>(x, y, nrows);
}